// round 1
// baseline (speedup 1.0000x reference)
#include <cuda_runtime.h>

#define N_NODES 6144
#define NFEAT   512
#define NHID    256
#define NHEADS  4
#define DHEAD   64
#define NEMBED  128
#define LRELU_ALPHA 0.2f
#define MAXDEG  256

// Scratch (device globals; no runtime allocation allowed)
__device__ float g_whcat[N_NODES * NHID];   // Wh in [node][head*64+d] layout
__device__ float g_s[NHEADS * N_NODES];
__device__ float g_t[NHEADS * N_NODES];
__device__ float g_hcat[N_NODES * NHID];    // post-attention, post-ELU hidden

// ---------------------------------------------------------------------------
// K1: Wh_cat = x @ W2, where W2[k][h*64+d] = W[h][k][d]
//     [6144,512] @ [512,256] -> [6144,256]
//     128x128 tile, BK=8, 256 threads, 8x8 microtile
// ---------------------------------------------------------------------------
__global__ __launch_bounds__(256) void k1_gemm(
    const float* __restrict__ x, const float* __restrict__ W,
    float* __restrict__ C)
{
    __shared__ float As[8][128];
    __shared__ float Bs[8][128];

    const int m0 = blockIdx.x * 128;
    const int c0 = blockIdx.y * 128;
    const int t  = threadIdx.x;
    const int tx = t & 15;   // col group
    const int ty = t >> 4;   // row group

    float acc[8][8];
#pragma unroll
    for (int i = 0; i < 8; i++)
#pragma unroll
        for (int j = 0; j < 8; j++) acc[i][j] = 0.f;

    // A-load mapping: row = t>>1 (0..127), kq = t&1 (two float4 per row of 8 k)
    const int a_row = t >> 1;
    const int a_kq  = t & 1;
    // B-load mapping: krow = t>>5 (0..7), cq = (t&31)*4 (0..124)
    const int b_k  = t >> 5;
    const int b_cq = (t & 31) << 2;
    const int b_c  = c0 + b_cq;
    const int b_head = b_c >> 6;
    const int b_d    = b_c & 63;

    for (int kk = 0; kk < NFEAT; kk += 8) {
        // load A tile (128 x 8)
        float4 av = *(const float4*)(x + (size_t)(m0 + a_row) * NFEAT + kk + a_kq * 4);
        As[a_kq * 4 + 0][a_row] = av.x;
        As[a_kq * 4 + 1][a_row] = av.y;
        As[a_kq * 4 + 2][a_row] = av.z;
        As[a_kq * 4 + 3][a_row] = av.w;
        // load B tile (8 x 128): W[head][kk+b_k][b_d .. b_d+3]
        float4 bv = *(const float4*)(W + (size_t)b_head * NFEAT * DHEAD
                                       + (size_t)(kk + b_k) * DHEAD + b_d);
        *(float4*)&Bs[b_k][b_cq] = bv;
        __syncthreads();

        float a[8], b[8];
#pragma unroll
        for (int k = 0; k < 8; k++) {
            *(float4*)(a + 0) = *(const float4*)&As[k][ty * 8 + 0];
            *(float4*)(a + 4) = *(const float4*)&As[k][ty * 8 + 4];
            *(float4*)(b + 0) = *(const float4*)&Bs[k][tx * 8 + 0];
            *(float4*)(b + 4) = *(const float4*)&Bs[k][tx * 8 + 4];
#pragma unroll
            for (int i = 0; i < 8; i++)
#pragma unroll
                for (int j = 0; j < 8; j++)
                    acc[i][j] += a[i] * b[j];
        }
        __syncthreads();
    }

#pragma unroll
    for (int i = 0; i < 8; i++) {
        float* dst = C + (size_t)(m0 + ty * 8 + i) * NHID + c0 + tx * 8;
        *(float4*)(dst + 0) = make_float4(acc[i][0], acc[i][1], acc[i][2], acc[i][3]);
        *(float4*)(dst + 4) = make_float4(acc[i][4], acc[i][5], acc[i][6], acc[i][7]);
    }
}

// ---------------------------------------------------------------------------
// K2: s[h][i] = Wh[h][i][:] . a_src[h],  t[h][i] = Wh[h][i][:] . a_dst[h]
// ---------------------------------------------------------------------------
__global__ __launch_bounds__(256) void k2_st(
    const float* __restrict__ wh, const float* __restrict__ a_src,
    const float* __restrict__ a_dst,
    float* __restrict__ s, float* __restrict__ t)
{
    int id = blockIdx.x * blockDim.x + threadIdx.x;
    if (id >= NHEADS * N_NODES) return;
    int h = id / N_NODES;
    int i = id - h * N_NODES;
    const float* row = wh + (size_t)i * NHID + h * DHEAD;
    const float* as  = a_src + h * DHEAD;
    const float* ad  = a_dst + h * DHEAD;
    float ss = 0.f, tt = 0.f;
#pragma unroll 8
    for (int d = 0; d < DHEAD; d++) {
        float v = row[d];
        ss += v * as[d];
        tt += v * ad[d];
    }
    s[id] = ss;
    t[id] = tt;
}

// ---------------------------------------------------------------------------
// K3: per-node sparse masked softmax + aggregation + per-head ELU
//     One block (256 thr) per node. Thread tid = (head = tid>>6, d = tid&63).
// ---------------------------------------------------------------------------
__global__ __launch_bounds__(256) void k3_attn(
    const int* __restrict__ adj, const float* __restrict__ wh,
    const float* __restrict__ s, const float* __restrict__ t,
    float* __restrict__ hcat)
{
    __shared__ int   sidx[MAXDEG];
    __shared__ float sw[NHEADS * MAXDEG];
    __shared__ float srs[NHEADS];
    __shared__ int   scount;

    const int i   = blockIdx.x;
    const int tid = threadIdx.x;
    if (tid == 0) scount = 0;
    __syncthreads();

    // Phase A: scan adjacency row, compact nonzero columns
    const int4* arow = (const int4*)(adj + (size_t)i * N_NODES);
    for (int q = tid; q < N_NODES / 4; q += 256) {
        int4 v = arow[q];
        if (v.x) { int p = atomicAdd(&scount, 1); if (p < MAXDEG) sidx[p] = q * 4 + 0; }
        if (v.y) { int p = atomicAdd(&scount, 1); if (p < MAXDEG) sidx[p] = q * 4 + 1; }
        if (v.z) { int p = atomicAdd(&scount, 1); if (p < MAXDEG) sidx[p] = q * 4 + 2; }
        if (v.w) { int p = atomicAdd(&scount, 1); if (p < MAXDEG) sidx[p] = q * 4 + 3; }
    }
    __syncthreads();
    const int deg = min(scount, MAXDEG);

    // Phase B: e[h][j] = lrelu(s[h][i] + t[h][j])
    for (int m = tid; m < deg * NHEADS; m += 256) {
        int j = m >> 2;
        int h = m & 3;
        int jj = sidx[j];
        float e = s[h * N_NODES + i] + t[h * N_NODES + jj];
        e = e > 0.f ? e : LRELU_ALPHA * e;
        sw[h * MAXDEG + j] = e;
    }
    __syncthreads();

    // Phase C: per-head softmax (warp h handles head h)
    const int warp = tid >> 5;
    const int lane = tid & 31;
    if (warp < NHEADS) {
        const int h = warp;
        float mx = -3.4e38f;
        for (int j = lane; j < deg; j += 32) mx = fmaxf(mx, sw[h * MAXDEG + j]);
#pragma unroll
        for (int o = 16; o; o >>= 1) mx = fmaxf(mx, __shfl_xor_sync(0xffffffffu, mx, o));
        float sum = 0.f;
        for (int j = lane; j < deg; j += 32) {
            float w = __expf(sw[h * MAXDEG + j] - mx);
            sw[h * MAXDEG + j] = w;
            sum += w;
        }
#pragma unroll
        for (int o = 16; o; o >>= 1) sum += __shfl_xor_sync(0xffffffffu, sum, o);
        if (lane == 0) srs[h] = (sum > 0.f) ? 1.f / sum : 0.f;
    }
    __syncthreads();

    // Phase D: aggregate h[i][h][d] = (1/sum) * sum_j w_j * Wh[j][h*64+d], then ELU
    const int h = tid >> 6;
    const int d = tid & 63;
    float acc = 0.f;
    const float* whb = wh + h * DHEAD + d;
#pragma unroll 4
    for (int j = 0; j < deg; j++) {
        int jj = sidx[j];
        acc += sw[h * MAXDEG + j] * whb[(size_t)jj * NHID];
    }
    acc *= srs[h];
    acc = acc > 0.f ? acc : (__expf(acc) - 1.f);
    hcat[(size_t)i * NHID + tid] = acc;
}

// ---------------------------------------------------------------------------
// K4: out = elu(hcat @ lin_w^T + b)   [6144,256]@[256,128] -> [6144,128]
//     64x64 tile, BK=16, 256 threads, 4x4 microtile
// ---------------------------------------------------------------------------
__global__ __launch_bounds__(256) void k4_out(
    const float* __restrict__ hcat, const float* __restrict__ lin_w,
    const float* __restrict__ lin_b, float* __restrict__ out)
{
    __shared__ float As[16][64];
    __shared__ float Bs[16][64];

    const int m0 = blockIdx.x * 64;
    const int n0 = blockIdx.y * 64;
    const int t  = threadIdx.x;
    const int tx = t & 15;
    const int ty = t >> 4;

    float acc[4][4];
#pragma unroll
    for (int i = 0; i < 4; i++)
#pragma unroll
        for (int j = 0; j < 4; j++) acc[i][j] = 0.f;

    const int l_row = t >> 2;   // 0..63
    const int l_kq  = t & 3;    // float4 within 16-wide k chunk

    for (int kk = 0; kk < NHID; kk += 16) {
        float4 av = *(const float4*)(hcat + (size_t)(m0 + l_row) * NHID + kk + l_kq * 4);
        As[l_kq * 4 + 0][l_row] = av.x;
        As[l_kq * 4 + 1][l_row] = av.y;
        As[l_kq * 4 + 2][l_row] = av.z;
        As[l_kq * 4 + 3][l_row] = av.w;
        float4 bv = *(const float4*)(lin_w + (size_t)(n0 + l_row) * NHID + kk + l_kq * 4);
        Bs[l_kq * 4 + 0][l_row] = bv.x;
        Bs[l_kq * 4 + 1][l_row] = bv.y;
        Bs[l_kq * 4 + 2][l_row] = bv.z;
        Bs[l_kq * 4 + 3][l_row] = bv.w;
        __syncthreads();

#pragma unroll
        for (int k = 0; k < 16; k++) {
            float a[4], b[4];
            *(float4*)a = *(const float4*)&As[k][ty * 4];
            *(float4*)b = *(const float4*)&Bs[k][tx * 4];
#pragma unroll
            for (int i = 0; i < 4; i++)
#pragma unroll
                for (int j = 0; j < 4; j++)
                    acc[i][j] += a[i] * b[j];
        }
        __syncthreads();
    }

#pragma unroll
    for (int i = 0; i < 4; i++) {
#pragma unroll
        for (int j = 0; j < 4; j++) {
            float v = acc[i][j] + lin_b[n0 + tx * 4 + j];
            v = v > 0.f ? v : (__expf(v) - 1.f);
            out[(size_t)(m0 + ty * 4 + i) * NEMBED + n0 + tx * 4 + j] = v;
        }
    }
}

// ---------------------------------------------------------------------------
extern "C" void kernel_launch(void* const* d_in, const int* in_sizes, int n_in,
                              void* d_out, int out_size)
{
    const float* x     = (const float*)d_in[0];
    const int*   adj   = (const int*)  d_in[1];
    const float* W     = (const float*)d_in[2];
    const float* a_src = (const float*)d_in[3];
    const float* a_dst = (const float*)d_in[4];
    const float* lin_w = (const float*)d_in[5];
    const float* lin_b = (const float*)d_in[6];
    float* out = (float*)d_out;

    float* whcat; cudaGetSymbolAddress((void**)&whcat, g_whcat);
    float* s;     cudaGetSymbolAddress((void**)&s, g_s);
    float* t;     cudaGetSymbolAddress((void**)&t, g_t);
    float* hcat;  cudaGetSymbolAddress((void**)&hcat, g_hcat);

    dim3 g1(N_NODES / 128, NHID / 128);
    k1_gemm<<<g1, 256>>>(x, W, whcat);

    k2_st<<<(NHEADS * N_NODES + 255) / 256, 256>>>(whcat, a_src, a_dst, s, t);

    k3_attn<<<N_NODES, 256>>>(adj, whcat, s, t, hcat);

    dim3 g4(N_NODES / 64, NEMBED / 64);
    k4_out<<<g4, 256>>>(hcat, lin_w, lin_b, out);
}